// round 8
// baseline (speedup 1.0000x reference)
#include <cuda_runtime.h>
#include <cuda_fp16.h>
#include <math.h>
#include <stdint.h>

#define T_TOK 4096
#define DIM   1024
#define NE    8
#define FF    4096
#define NPAIR (2*T_TOK)
#define CAPP  9216             // 8192 + 8*128 padding (segments 128-aligned)

// ---------------- scratch (device globals) ----------------------------------
__device__ __half g_Hh[(size_t)CAPP * FF];
__device__ __half g_xh[(size_t)T_TOK * DIM];
__device__ __half g_w1h[(size_t)NE * DIM * FF];
__device__ __half g_w2h[(size_t)NE * FF * DIM];
__device__ float g_gwc[DIM * NE];          // gate_w + noise_w combined
__device__ int   g_pair_tok[CAPP];
__device__ float g_pair_sc[CAPP];
__device__ int   g_tok_e[NPAIR];
__device__ float g_tok_p[NPAIR];
__device__ int   g_counts[NE];
__device__ int   g_cursor[NE];
__device__ int   g_seg[NE + 1];

// ---------------- helpers ----------------------------------------------------
__device__ __forceinline__ uint32_t smem_u32(const void* p) {
    return (uint32_t)__cvta_generic_to_shared(p);
}
__device__ __forceinline__ uint32_t pack_h2(float a, float b) {
    __half2 h = __floats2half2_rn(a, b);
    return *(uint32_t*)&h;
}
__device__ __forceinline__ void mma_f16(float& c0, float& c1, float& c2, float& c3,
                                        uint32_t a0, uint32_t a1, uint32_t a2, uint32_t a3,
                                        uint32_t b0, uint32_t b1) {
    asm volatile(
        "mma.sync.aligned.m16n8k16.row.col.f32.f16.f16.f32 "
        "{%0,%1,%2,%3}, {%4,%5,%6,%7}, {%8,%9}, {%0,%1,%2,%3};"
        : "+f"(c0), "+f"(c1), "+f"(c2), "+f"(c3)
        : "r"(a0), "r"(a1), "r"(a2), "r"(a3), "r"(b0), "r"(b1));
}
__device__ __forceinline__ void ldsm_x4(uint32_t& r0, uint32_t& r1, uint32_t& r2,
                                        uint32_t& r3, uint32_t addr) {
    asm volatile("ldmatrix.sync.aligned.m8n8.x4.shared.b16 {%0,%1,%2,%3}, [%4];"
                 : "=r"(r0), "=r"(r1), "=r"(r2), "=r"(r3) : "r"(addr));
}
__device__ __forceinline__ void ldsm_x4t(uint32_t& r0, uint32_t& r1, uint32_t& r2,
                                         uint32_t& r3, uint32_t addr) {
    asm volatile("ldmatrix.sync.aligned.m8n8.x4.trans.shared.b16 {%0,%1,%2,%3}, [%4];"
                 : "=r"(r0), "=r"(r1), "=r"(r2), "=r"(r3) : "r"(addr));
}
__device__ __forceinline__ void cpa16(uint32_t dst, const void* src) {
    asm volatile("cp.async.cg.shared.global [%0], [%1], 16;"
                 :: "r"(dst), "l"(src));
}
#define CP_COMMIT() asm volatile("cp.async.commit_group;" ::: "memory")
#define CP_WAIT3()  asm volatile("cp.async.wait_group 3;"  ::: "memory")

// ---------------- setup kernels ---------------------------------------------
// fused: zero out accumulator + reset counters + init pair arrays + gw+nw sum
__global__ void k_setup(float4* out, const float* __restrict__ gw,
                        const float* __restrict__ nw) {
    int i = blockIdx.x * blockDim.x + threadIdx.x;
    if (i < T_TOK * DIM / 4) out[i] = make_float4(0.f, 0.f, 0.f, 0.f);
    if (i < CAPP) { g_pair_tok[i] = -1; g_pair_sc[i] = 0.f; }
    if (i < DIM * NE) g_gwc[i] = gw[i] + nw[i];
    if (i < NE) { g_counts[i] = 0; g_cursor[i] = 0; }
}
// fp32 -> fp16 bulk convert (8 elems / thread)
__global__ void k_cvt(const float4* __restrict__ src, uint4* __restrict__ dst, int n8) {
    int i = blockIdx.x * blockDim.x + threadIdx.x;
    if (i >= n8) return;
    float4 v0 = src[2 * i], v1 = src[2 * i + 1];
    dst[i] = make_uint4(pack_h2(v0.x, v0.y), pack_h2(v0.z, v0.w),
                        pack_h2(v1.x, v1.y), pack_h2(v1.z, v1.w));
}

// ---------------- router ------------------------------------------------------
__global__ void __launch_bounds__(128) k_router(
    const float* __restrict__ x, const float* __restrict__ noise,
    const float* __restrict__ gb, const float* __restrict__ nb)
{
    int t = blockIdx.x;
    int tid = threadIdx.x;
    __shared__ float sx[DIM];
    __shared__ float red[128];
    __shared__ float lg[NE];

    for (int i = tid; i < DIM; i += 128) sx[i] = x[(size_t)t * DIM + i];
    __syncthreads();
    for (int i = tid; i < DIM / 2; i += 128)
        *(uint32_t*)&g_xh[(size_t)t * DIM + 2 * i] = pack_h2(sx[2 * i], sx[2 * i + 1]);

    int e = tid & 7;
    float s = 0.f;
    for (int d = (tid >> 3); d < DIM; d += 16)
        s += sx[d] * g_gwc[d * NE + e];
    red[tid] = s;
    __syncthreads();
    for (int off = 64; off >= 8; off >>= 1) {
        if (tid < off) red[tid] += red[tid + off];
        __syncthreads();
    }
    if (tid < NE)
        lg[tid] = red[tid] + gb[tid] + nb[tid] + noise[t * NE + tid];
    __syncthreads();

    if (tid == 0) {
        float v0 = -1e30f; int i0 = 0;
        #pragma unroll
        for (int k = 0; k < NE; k++) { float v = lg[k]; if (v > v0) { v0 = v; i0 = k; } }
        float v1 = -1e30f; int i1 = 0;
        #pragma unroll
        for (int k = 0; k < NE; k++) { if (k == i0) continue; float v = lg[k]; if (v > v1) { v1 = v; i1 = k; } }
        float e1 = expf(v1 - v0);
        float z = 1.f + e1;
        g_tok_e[2 * t] = i0;  g_tok_e[2 * t + 1] = i1;
        g_tok_p[2 * t] = 1.f / z;  g_tok_p[2 * t + 1] = e1 / z;
        atomicAdd(&g_counts[i0], 1);
        atomicAdd(&g_counts[i1], 1);
    }
}

__global__ void k_offsets() {
    if (threadIdx.x == 0) {
        int acc = 0;
        g_seg[0] = 0;
        for (int e = 0; e < NE; e++) {
            acc += ((g_counts[e] + 127) / 128) * 128;
            g_seg[e + 1] = acc;
        }
    }
}
__global__ void k_scatter() {
    int i = blockIdx.x * blockDim.x + threadIdx.x;
    if (i >= NPAIR) return;
    int t = i >> 1;
    int e = g_tok_e[i];
    float p = g_tok_p[i];
    int pos = g_seg[e] + atomicAdd(&g_cursor[e], 1);
    g_pair_tok[pos] = t;
    g_pair_sc[pos]  = p;
}
__device__ __forceinline__ int tile_expert(int row0) {
    int e = -1;
    #pragma unroll
    for (int i = 0; i < NE; i++)
        if (row0 >= g_seg[i] && row0 < g_seg[i + 1]) e = i;
    return e;
}

// ---------------- SMEM geometry (halfs) --------------------------------------
#define NTILE 256
#define AST 40                   // A row stride (80B) - LDSM conflict-free
#define BST 264                  // B row stride (528B) - 4r%32 distinct, conflict-free
#define A_STAGE_H (128 * AST)    // 5120 halfs
#define B_STAGE_H (32 * BST)     // 8448 halfs
#define NSTAGE 4
#define GEMM_SMEM ((A_STAGE_H + B_STAGE_H) * NSTAGE * 2)   // 108544 B

// =============================================================================
// fp16 mma.sync GEMM: 128M x 256N CTA tile, 8 warps (64x64 each), K-tile 32,
// 4-stage cp.async, R5 issue-ahead order. 1 CTA/SM.
// =============================================================================

// GEMM1: g_Hh = fp16(SiLU(Xh_gather @ W1h[e] + b1[e]))
__global__ void __launch_bounds__(256, 1) k_mma_gemm1(const float* __restrict__ b1)
{
    extern __shared__ __half sm[];
    __half* As = sm;                            // [NSTAGE][128][AST]
    __half* Bs = sm + NSTAGE * A_STAGE_H;       // [NSTAGE][32][BST]
    __shared__ int stok[128];

    const int tid = threadIdx.x;
    const int n0 = blockIdx.x * NTILE;
    const int row0 = blockIdx.y * 128;
    const int e = tile_expert(row0);
    if (e < 0) return;
    const __half* __restrict__ w = g_w1h + (size_t)e * DIM * FF;

    if (tid < 128) stok[tid] = g_pair_tok[row0 + tid];
    __syncthreads();

    const int lane = tid & 31;
    const int wrp = tid >> 5;
    const int wm = (wrp & 1) * 64;
    const int wn = (wrp >> 1) * 64;
    const int qr = lane >> 2;
    const uint32_t as_base = smem_u32(As);
    const uint32_t bs_base = smem_u32(Bs);

    // A staging: rows ar, ar+64; 8 halfs each
    const int ar = tid >> 2;
    const int ac8 = (tid & 3) * 8;
    int ta0 = stok[ar];      if (ta0 < 0) ta0 = 0;
    int ta1 = stok[ar + 64]; if (ta1 < 0) ta1 = 0;
    const __half* xr0 = g_xh + (size_t)ta0 * DIM + ac8;
    const __half* xr1 = g_xh + (size_t)ta1 * DIM + ac8;
    const uint32_t a_d0 = as_base + (ar * AST + ac8) * 2;
    const uint32_t a_d1 = as_base + ((ar + 64) * AST + ac8) * 2;
    // B staging: rows br, br+8, br+16, br+24; 8 halfs each at col bc8
    const int br = tid >> 5;               // 0..7
    const int bc8 = (tid & 31) * 8;        // 0..248
    const __half* wr = w + n0 + bc8;
    const uint32_t b_d0 = bs_base + (br * BST + bc8) * 2;

    // LDSM lane offsets
    const int a_r = (lane & 15);
    const int a_k = (lane & 16) >> 1;
    const int b_k = (lane & 7) + ((lane & 8) ? 8 : 0);
    const int b_n = (lane & 16) >> 1;

    float acc[4][8][4];
    #pragma unroll
    for (int i = 0; i < 4; i++)
        #pragma unroll
        for (int j = 0; j < 8; j++)
            #pragma unroll
            for (int q = 0; q < 4; q++) acc[i][j][q] = 0.f;

    const int NK = DIM / 32;
    #pragma unroll
    for (int s = 0; s < NSTAGE - 1; ++s) {
        int kt = s * 32;
        uint32_t ao = s * A_STAGE_H * 2, bo = s * B_STAGE_H * 2;
        cpa16(a_d0 + ao, xr0 + kt);
        cpa16(a_d1 + ao, xr1 + kt);
        #pragma unroll
        for (int m = 0; m < 4; ++m)
            cpa16(b_d0 + bo + m * 8 * BST * 2, wr + (size_t)(kt + br + m * 8) * FF);
        CP_COMMIT();
    }

    for (int ki = 0; ki < NK; ++ki) {
        int kf = ki + NSTAGE - 1;
        if (kf < NK) {
            int s = kf % NSTAGE;
            int kt = kf * 32;
            uint32_t ao = s * A_STAGE_H * 2, bo = s * B_STAGE_H * 2;
            cpa16(a_d0 + ao, xr0 + kt);
            cpa16(a_d1 + ao, xr1 + kt);
            #pragma unroll
            for (int m = 0; m < 4; ++m)
                cpa16(b_d0 + bo + m * 8 * BST * 2, wr + (size_t)(kt + br + m * 8) * FF);
        }
        CP_COMMIT();
        CP_WAIT3();
        __syncthreads();

        const int s = ki % NSTAGE;
        const uint32_t asb = as_base + s * A_STAGE_H * 2;
        const uint32_t bsb = bs_base + s * B_STAGE_H * 2;
        #pragma unroll
        for (int ks = 0; ks < 2; ++ks) {
            const int k0 = ks * 16;
            uint32_t af[4][4];
            #pragma unroll
            for (int i = 0; i < 4; ++i) {
                uint32_t ad = asb + ((wm + i * 16 + a_r) * AST + k0 + a_k) * 2;
                ldsm_x4(af[i][0], af[i][1], af[i][2], af[i][3], ad);
            }
            uint32_t bf[8][2];
            #pragma unroll
            for (int jp = 0; jp < 4; ++jp) {
                uint32_t bd = bsb + ((k0 + b_k) * BST + wn + jp * 16 + b_n) * 2;
                ldsm_x4t(bf[jp * 2][0], bf[jp * 2][1],
                         bf[jp * 2 + 1][0], bf[jp * 2 + 1][1], bd);
            }
            #pragma unroll
            for (int i = 0; i < 4; ++i)
                #pragma unroll
                for (int j = 0; j < 8; ++j)
                    mma_f16(acc[i][j][0], acc[i][j][1], acc[i][j][2], acc[i][j][3],
                            af[i][0], af[i][1], af[i][2], af[i][3],
                            bf[j][0], bf[j][1]);
        }
        __syncthreads();
    }

    // epilogue: bias + SiLU -> g_Hh (fp16)
    const float* bp = b1 + (size_t)e * FF + n0;
    #pragma unroll
    for (int j = 0; j < 8; ++j) {
        int col = wn + j * 8 + (lane & 3) * 2;
        float bb0 = bp[col], bb1 = bp[col + 1];
        #pragma unroll
        for (int i = 0; i < 4; ++i) {
            int r0 = row0 + wm + i * 16 + qr;
            float a0 = acc[i][j][0] + bb0, a1 = acc[i][j][1] + bb1;
            uint32_t p0 = pack_h2(a0 / (1.f + __expf(-a0)), a1 / (1.f + __expf(-a1)));
            *(uint32_t*)&g_Hh[(size_t)r0 * FF + n0 + col] = p0;
            float a2 = acc[i][j][2] + bb0, a3 = acc[i][j][3] + bb1;
            uint32_t p1 = pack_h2(a2 / (1.f + __expf(-a2)), a3 / (1.f + __expf(-a3)));
            *(uint32_t*)&g_Hh[(size_t)(r0 + 8) * FF + n0 + col] = p1;
        }
    }
}

// GEMM2: out[t] += score * (g_Hh @ W2h[e] + b2[e])
__global__ void __launch_bounds__(256, 1) k_mma_gemm2(
    const float* __restrict__ b2, float* __restrict__ out)
{
    extern __shared__ __half sm[];
    __half* As = sm;
    __half* Bs = sm + NSTAGE * A_STAGE_H;
    __shared__ int   stok[128];
    __shared__ float ssc[128];

    const int tid = threadIdx.x;
    const int n0 = blockIdx.x * NTILE;
    const int row0 = blockIdx.y * 128;
    const int e = tile_expert(row0);
    if (e < 0) return;
    const __half* __restrict__ w = g_w2h + (size_t)e * FF * DIM;

    if (tid < 128) { stok[tid] = g_pair_tok[row0 + tid]; ssc[tid] = g_pair_sc[row0 + tid]; }
    __syncthreads();

    const int lane = tid & 31;
    const int wrp = tid >> 5;
    const int wm = (wrp & 1) * 64;
    const int wn = (wrp >> 1) * 64;
    const int qr = lane >> 2;
    const uint32_t as_base = smem_u32(As);
    const uint32_t bs_base = smem_u32(Bs);

    const int ar = tid >> 2;
    const int ac8 = (tid & 3) * 8;
    const __half* hr0 = g_Hh + (size_t)(row0 + ar) * FF + ac8;
    const __half* hr1 = g_Hh + (size_t)(row0 + ar + 64) * FF + ac8;
    const uint32_t a_d0 = as_base + (ar * AST + ac8) * 2;
    const uint32_t a_d1 = as_base + ((ar + 64) * AST + ac8) * 2;
    const int br = tid >> 5;
    const int bc8 = (tid & 31) * 8;
    const __half* wr = w + n0 + bc8;
    const uint32_t b_d0 = bs_base + (br * BST + bc8) * 2;

    const int a_r = (lane & 15);
    const int a_k = (lane & 16) >> 1;
    const int b_k = (lane & 7) + ((lane & 8) ? 8 : 0);
    const int b_n = (lane & 16) >> 1;

    float acc[4][8][4];
    #pragma unroll
    for (int i = 0; i < 4; i++)
        #pragma unroll
        for (int j = 0; j < 8; j++)
            #pragma unroll
            for (int q = 0; q < 4; q++) acc[i][j][q] = 0.f;

    const int NK = FF / 32;
    #pragma unroll
    for (int s = 0; s < NSTAGE - 1; ++s) {
        int kt = s * 32;
        uint32_t ao = s * A_STAGE_H * 2, bo = s * B_STAGE_H * 2;
        cpa16(a_d0 + ao, hr0 + kt);
        cpa16(a_d1 + ao, hr1 + kt);
        #pragma unroll
        for (int m = 0; m < 4; ++m)
            cpa16(b_d0 + bo + m * 8 * BST * 2, wr + (size_t)(kt + br + m * 8) * DIM);
        CP_COMMIT();
    }

    for (int ki = 0; ki < NK; ++ki) {
        int kf = ki + NSTAGE - 1;
        if (kf < NK) {
            int s = kf % NSTAGE;
            int kt = kf * 32;
            uint32_t ao = s * A_STAGE_H * 2, bo = s * B_STAGE_H * 2;
            cpa16(a_d0 + ao, hr0 + kt);
            cpa16(a_d1 + ao, hr1 + kt);
            #pragma unroll
            for (int m = 0; m < 4; ++m)
                cpa16(b_d0 + bo + m * 8 * BST * 2, wr + (size_t)(kt + br + m * 8) * DIM);
        }
        CP_COMMIT();
        CP_WAIT3();
        __syncthreads();

        const int s = ki % NSTAGE;
        const uint32_t asb = as_base + s * A_STAGE_H * 2;
        const uint32_t bsb = bs_base + s * B_STAGE_H * 2;
        #pragma unroll
        for (int ks = 0; ks < 2; ++ks) {
            const int k0 = ks * 16;
            uint32_t af[4][4];
            #pragma unroll
            for (int i = 0; i < 4; ++i) {
                uint32_t ad = asb + ((wm + i * 16 + a_r) * AST + k0 + a_k) * 2;
                ldsm_x4(af[i][0], af[i][1], af[i][2], af[i][3], ad);
            }
            uint32_t bf[8][2];
            #pragma unroll
            for (int jp = 0; jp < 4; ++jp) {
                uint32_t bd = bsb + ((k0 + b_k) * BST + wn + jp * 16 + b_n) * 2;
                ldsm_x4t(bf[jp * 2][0], bf[jp * 2][1],
                         bf[jp * 2 + 1][0], bf[jp * 2 + 1][1], bd);
            }
            #pragma unroll
            for (int i = 0; i < 4; ++i)
                #pragma unroll
                for (int j = 0; j < 8; ++j)
                    mma_f16(acc[i][j][0], acc[i][j][1], acc[i][j][2], acc[i][j][3],
                            af[i][0], af[i][1], af[i][2], af[i][3],
                            bf[j][0], bf[j][1]);
        }
        __syncthreads();
    }

    // epilogue: bias + score * atomicAdd
    const float* bp = b2 + (size_t)e * DIM + n0;
    #pragma unroll
    for (int j = 0; j < 8; ++j) {
        int col = wn + j * 8 + (lane & 3) * 2;
        float bb0 = bp[col], bb1 = bp[col + 1];
        #pragma unroll
        for (int i = 0; i < 4; ++i) {
            int m = wm + i * 16 + qr;
            int t0 = stok[m], t1 = stok[m + 8];
            if (t0 >= 0) {
                float s = ssc[m];
                atomicAdd(&out[(size_t)t0 * DIM + n0 + col],     s * (acc[i][j][0] + bb0));
                atomicAdd(&out[(size_t)t0 * DIM + n0 + col + 1], s * (acc[i][j][1] + bb1));
            }
            if (t1 >= 0) {
                float s = ssc[m + 8];
                atomicAdd(&out[(size_t)t1 * DIM + n0 + col],     s * (acc[i][j][2] + bb0));
                atomicAdd(&out[(size_t)t1 * DIM + n0 + col + 1], s * (acc[i][j][3] + bb1));
            }
        }
    }
}

// ---------------- aux loss ---------------------------------------------------
__global__ void __launch_bounds__(256) k_aux(float* __restrict__ aux_out) {
    __shared__ float sred[256];
    __shared__ float simp[NE];
    int tid = threadIdx.x;
    float imp[NE];
    #pragma unroll
    for (int e = 0; e < NE; e++) imp[e] = 0.f;
    for (int t = tid; t < T_TOK; t += 256) {
        imp[g_tok_e[2 * t]]     += g_tok_p[2 * t];
        imp[g_tok_e[2 * t + 1]] += g_tok_p[2 * t + 1];
    }
    for (int e = 0; e < NE; e++) {
        sred[tid] = imp[e];
        __syncthreads();
        for (int off = 128; off > 0; off >>= 1) {
            if (tid < off) sred[tid] += sred[tid + off];
            __syncthreads();
        }
        if (tid == 0) simp[e] = sred[0] / (float)T_TOK;
        __syncthreads();
    }
    if (tid == 0) {
        float aux = 0.f;
        const float u = 1.f / (float)NE;
        const float logu = logf(u);
        #pragma unroll
        for (int e = 0; e < NE; e++)
            aux += u * (logu - logf(simp[e] + 1e-8f));
        aux_out[0] = aux;
    }
}

// ---------------- launch -----------------------------------------------------
extern "C" void kernel_launch(void* const* d_in, const int* in_sizes, int n_in,
                              void* d_out, int out_size) {
    const float* x       = (const float*)d_in[0];
    const float* noise   = (const float*)d_in[1];
    const float* gate_w  = (const float*)d_in[2];
    const float* gate_b  = (const float*)d_in[3];
    const float* noise_w = (const float*)d_in[4];
    const float* noise_b = (const float*)d_in[5];
    const float* w1      = (const float*)d_in[6];
    const float* b1      = (const float*)d_in[7];
    const float* w2      = (const float*)d_in[8];
    const float* b2      = (const float*)d_in[9];
    float* out = (float*)d_out;
    (void)in_sizes; (void)n_in;

    static bool attr_done = false;
    if (!attr_done) {
        cudaFuncSetAttribute(k_mma_gemm1, cudaFuncAttributeMaxDynamicSharedMemorySize, GEMM_SMEM);
        cudaFuncSetAttribute(k_mma_gemm2, cudaFuncAttributeMaxDynamicSharedMemorySize, GEMM_SMEM);
        attr_done = true;
    }

    __half* d_w1h; cudaGetSymbolAddress((void**)&d_w1h, g_w1h);
    __half* d_w2h; cudaGetSymbolAddress((void**)&d_w2h, g_w2h);
    {
        int n8 = NE * DIM * FF / 8;
        k_cvt<<<(n8 + 255) / 256, 256>>>((const float4*)w1, (uint4*)d_w1h, n8);
        k_cvt<<<(n8 + 255) / 256, 256>>>((const float4*)w2, (uint4*)d_w2h, n8);
    }

    k_setup<<<(T_TOK * DIM / 4 + 255) / 256, 256>>>((float4*)out, gate_w, noise_w);
    k_router<<<T_TOK, 128>>>(x, noise, gate_b, noise_b);
    k_offsets<<<1, 32>>>();
    k_scatter<<<(NPAIR + 255) / 256, 256>>>();
    k_mma_gemm1<<<dim3(FF / NTILE, CAPP / 128), 256, GEMM_SMEM>>>(b1);
    k_mma_gemm2<<<dim3(DIM / NTILE, CAPP / 128), 256, GEMM_SMEM>>>(b2, out);
    k_aux<<<1, 256>>>(out + (out_size - 1));
}

// round 9
// speedup vs baseline: 1.0656x; 1.0656x over previous
#include <cuda_runtime.h>
#include <cuda_fp16.h>
#include <math.h>
#include <stdint.h>

#define T_TOK 4096
#define DIM   1024
#define NE    8
#define FF    4096
#define NPAIR (2*T_TOK)
#define CAPP  9216             // 8192 + 8*128 padding (segments 128-aligned)

// ---------------- scratch (device globals) ----------------------------------
__device__ __half g_Hh[(size_t)CAPP * FF];
__device__ __half g_xh[(size_t)T_TOK * DIM];
__device__ __half g_w1h[(size_t)NE * DIM * FF];
__device__ __half g_w2h[(size_t)NE * FF * DIM];
__device__ float g_gwc[DIM * NE];          // gate_w + noise_w combined
__device__ int   g_pair_tok[CAPP];
__device__ float g_pair_sc[CAPP];
__device__ int   g_tok_e[NPAIR];
__device__ float g_tok_p[NPAIR];
__device__ int   g_counts[NE];
__device__ int   g_cursor[NE];
__device__ int   g_seg[NE + 1];

// ---------------- helpers ----------------------------------------------------
__device__ __forceinline__ uint32_t smem_u32(const void* p) {
    return (uint32_t)__cvta_generic_to_shared(p);
}
__device__ __forceinline__ uint32_t pack_h2(float a, float b) {
    __half2 h = __floats2half2_rn(a, b);
    return *(uint32_t*)&h;
}
__device__ __forceinline__ void mma_f16(float& c0, float& c1, float& c2, float& c3,
                                        uint32_t a0, uint32_t a1, uint32_t a2, uint32_t a3,
                                        uint32_t b0, uint32_t b1) {
    asm volatile(
        "mma.sync.aligned.m16n8k16.row.col.f32.f16.f16.f32 "
        "{%0,%1,%2,%3}, {%4,%5,%6,%7}, {%8,%9}, {%0,%1,%2,%3};"
        : "+f"(c0), "+f"(c1), "+f"(c2), "+f"(c3)
        : "r"(a0), "r"(a1), "r"(a2), "r"(a3), "r"(b0), "r"(b1));
}
__device__ __forceinline__ void ldsm_x4(uint32_t& r0, uint32_t& r1, uint32_t& r2,
                                        uint32_t& r3, uint32_t addr) {
    asm volatile("ldmatrix.sync.aligned.m8n8.x4.shared.b16 {%0,%1,%2,%3}, [%4];"
                 : "=r"(r0), "=r"(r1), "=r"(r2), "=r"(r3) : "r"(addr));
}
__device__ __forceinline__ void ldsm_x4t(uint32_t& r0, uint32_t& r1, uint32_t& r2,
                                         uint32_t& r3, uint32_t addr) {
    asm volatile("ldmatrix.sync.aligned.m8n8.x4.trans.shared.b16 {%0,%1,%2,%3}, [%4];"
                 : "=r"(r0), "=r"(r1), "=r"(r2), "=r"(r3) : "r"(addr));
}
__device__ __forceinline__ void cpa16(uint32_t dst, const void* src) {
    asm volatile("cp.async.cg.shared.global [%0], [%1], 16;"
                 :: "r"(dst), "l"(src));
}
#define CP_COMMIT() asm volatile("cp.async.commit_group;" ::: "memory")
#define CP_WAITN()  asm volatile("cp.async.wait_group 4;"  ::: "memory")

// ---------------- setup kernels ---------------------------------------------
__global__ void k_setup(float4* out, const float* __restrict__ gw,
                        const float* __restrict__ nw) {
    int i = blockIdx.x * blockDim.x + threadIdx.x;
    if (i < T_TOK * DIM / 4) out[i] = make_float4(0.f, 0.f, 0.f, 0.f);
    if (i < CAPP) { g_pair_tok[i] = -1; g_pair_sc[i] = 0.f; }
    if (i < DIM * NE) g_gwc[i] = gw[i] + nw[i];
    if (i < NE) { g_counts[i] = 0; g_cursor[i] = 0; }
}
// fp32 -> fp16 bulk convert of BOTH weight tensors in one launch
__global__ void k_cvtw(const float4* __restrict__ w1, const float4* __restrict__ w2,
                       uint4* __restrict__ d1, uint4* __restrict__ d2) {
    const int n8 = NE * DIM * FF / 8;
    int i = blockIdx.x * blockDim.x + threadIdx.x;
    const float4* src; uint4* dst;
    if (i < n8) { src = w1; dst = d1; }
    else        { i -= n8; src = w2; dst = d2; }
    float4 v0 = src[2 * i], v1 = src[2 * i + 1];
    dst[i] = make_uint4(pack_h2(v0.x, v0.y), pack_h2(v0.z, v0.w),
                        pack_h2(v1.x, v1.y), pack_h2(v1.z, v1.w));
}

// ---------------- router: 8 tokens / 256-thread block ------------------------
__global__ void __launch_bounds__(256) k_router(
    const float* __restrict__ x, const float* __restrict__ noise,
    const float* __restrict__ gb, const float* __restrict__ nb)
{
    __shared__ float sx[8 * DIM];   // 32 KB
    __shared__ float sl[64];
    const int tid = threadIdx.x;
    const int t0 = blockIdx.x * 8;

    for (int i = tid; i < 8 * DIM / 4; i += 256) {
        float4 v = ((const float4*)(x + (size_t)t0 * DIM))[i];
        *(float4*)&sx[i * 4] = v;
    }
    __syncthreads();
    // x -> fp16
    for (int i = tid; i < 8 * DIM / 2; i += 256) {
        *(uint32_t*)&g_xh[(size_t)t0 * DIM + 2 * i] = pack_h2(sx[2 * i], sx[2 * i + 1]);
    }
    // logits: pair p = (token, expert), 4 threads per pair
    const int p = tid >> 2;          // 0..63
    const int q = tid & 3;
    const int tok = p >> 3, e = p & 7;
    const float* xr = &sx[tok * DIM];
    float s = 0.f;
    #pragma unroll 4
    for (int k = q; k < DIM; k += 4)
        s += xr[k] * g_gwc[k * NE + e];
    s += __shfl_down_sync(0xffffffffu, s, 1);
    s += __shfl_down_sync(0xffffffffu, s, 2);
    if (q == 0) sl[p] = s;
    __syncthreads();

    if (tid < 8) {
        int t = t0 + tid;
        float lg[NE];
        #pragma unroll
        for (int k = 0; k < NE; k++)
            lg[k] = sl[tid * NE + k] + gb[k] + nb[k] + noise[t * NE + k];
        float v0 = -1e30f; int i0 = 0;
        #pragma unroll
        for (int k = 0; k < NE; k++) { if (lg[k] > v0) { v0 = lg[k]; i0 = k; } }
        float v1 = -1e30f; int i1 = 0;
        #pragma unroll
        for (int k = 0; k < NE; k++) { if (k == i0) continue; if (lg[k] > v1) { v1 = lg[k]; i1 = k; } }
        float e1 = expf(v1 - v0);
        float z = 1.f + e1;
        g_tok_e[2 * t] = i0;  g_tok_e[2 * t + 1] = i1;
        g_tok_p[2 * t] = 1.f / z;  g_tok_p[2 * t + 1] = e1 / z;
        atomicAdd(&g_counts[i0], 1);
        atomicAdd(&g_counts[i1], 1);
    }
}

__global__ void k_offsets() {
    if (threadIdx.x == 0) {
        int acc = 0;
        g_seg[0] = 0;
        for (int e = 0; e < NE; e++) {
            acc += ((g_counts[e] + 127) / 128) * 128;
            g_seg[e + 1] = acc;
        }
    }
}
__global__ void k_scatter() {
    int i = blockIdx.x * blockDim.x + threadIdx.x;
    if (i >= NPAIR) return;
    int t = i >> 1;
    int e = g_tok_e[i];
    float p = g_tok_p[i];
    int pos = g_seg[e] + atomicAdd(&g_cursor[e], 1);
    g_pair_tok[pos] = t;
    g_pair_sc[pos]  = p;
}
__device__ __forceinline__ int tile_expert(int row0) {
    int e = -1;
    #pragma unroll
    for (int i = 0; i < NE; i++)
        if (row0 >= g_seg[i] && row0 < g_seg[i + 1]) e = i;
    return e;
}

// ---------------- SMEM geometry (halfs) --------------------------------------
#define AST 40
#define BST 136
#define A_STAGE_H (128 * AST)    // 5120 halfs
#define B_STAGE_H (32 * BST)     // 4352 halfs
#define NSTAGE 5
#define GEMM_SMEM ((A_STAGE_H + B_STAGE_H) * NSTAGE * 2)   // 94720 B

// =============================================================================
// fp16 mma.sync GEMM, 128x128 CTA tile, 8 warps, K-tile 32, 5-stage cp.async
// (R7-proven structure)
// =============================================================================

__global__ void __launch_bounds__(256, 2) k_mma_gemm1(const float* __restrict__ b1)
{
    extern __shared__ __half sm[];
    __half* As = sm;
    __half* Bs = sm + NSTAGE * A_STAGE_H;
    __shared__ int stok[128];

    const int tid = threadIdx.x;
    const int n0 = blockIdx.x * 128;
    const int row0 = blockIdx.y * 128;
    const int e = tile_expert(row0);
    if (e < 0) return;
    const __half* __restrict__ w = g_w1h + (size_t)e * DIM * FF;

    if (tid < 128) stok[tid] = g_pair_tok[row0 + tid];
    __syncthreads();

    const int lane = tid & 31;
    const int wrp = tid >> 5;
    const int wm = (wrp & 1) * 64;
    const int wn = (wrp >> 1) * 32;
    const int qr = lane >> 2;
    const uint32_t as_base = smem_u32(As);
    const uint32_t bs_base = smem_u32(Bs);

    const int ar = tid >> 2;
    const int ac8 = (tid & 3) * 8;
    int ta0 = stok[ar];      if (ta0 < 0) ta0 = 0;
    int ta1 = stok[ar + 64]; if (ta1 < 0) ta1 = 0;
    const __half* xr0 = g_xh + (size_t)ta0 * DIM + ac8;
    const __half* xr1 = g_xh + (size_t)ta1 * DIM + ac8;
    const int br = tid >> 4;
    const int bc8 = (tid & 15) * 8;
    const __half* wr = w + n0 + bc8;

    const uint32_t a_d0 = as_base + (ar * AST + ac8) * 2;
    const uint32_t a_d1 = as_base + ((ar + 64) * AST + ac8) * 2;
    const uint32_t b_d0 = bs_base + (br * BST + bc8) * 2;
    const uint32_t b_d1 = bs_base + ((br + 16) * BST + bc8) * 2;

    const int a_r = (lane & 15);
    const int a_k = (lane & 16) >> 1;
    const int b_k = (lane & 7) + ((lane & 8) ? 8 : 0);
    const int b_n = (lane & 16) >> 1;

    float acc[4][4][4];
    #pragma unroll
    for (int i = 0; i < 4; i++)
        #pragma unroll
        for (int j = 0; j < 4; j++)
            #pragma unroll
            for (int q = 0; q < 4; q++) acc[i][j][q] = 0.f;

    const int NK = DIM / 32;
    #pragma unroll
    for (int s = 0; s < NSTAGE - 1; ++s) {
        int kt = s * 32;
        uint32_t ao = s * A_STAGE_H * 2, bo = s * B_STAGE_H * 2;
        cpa16(a_d0 + ao, xr0 + kt);
        cpa16(a_d1 + ao, xr1 + kt);
        cpa16(b_d0 + bo, wr + (size_t)(kt + br) * FF);
        cpa16(b_d1 + bo, wr + (size_t)(kt + br + 16) * FF);
        CP_COMMIT();
    }

    for (int ki = 0; ki < NK; ++ki) {
        int kf = ki + NSTAGE - 1;
        if (kf < NK) {
            int s = kf % NSTAGE;
            int kt = kf * 32;
            uint32_t ao = s * A_STAGE_H * 2, bo = s * B_STAGE_H * 2;
            cpa16(a_d0 + ao, xr0 + kt);
            cpa16(a_d1 + ao, xr1 + kt);
            cpa16(b_d0 + bo, wr + (size_t)(kt + br) * FF);
            cpa16(b_d1 + bo, wr + (size_t)(kt + br + 16) * FF);
        }
        CP_COMMIT();
        CP_WAITN();
        __syncthreads();

        const int s = ki % NSTAGE;
        const uint32_t asb = as_base + s * A_STAGE_H * 2;
        const uint32_t bsb = bs_base + s * B_STAGE_H * 2;
        #pragma unroll
        for (int ks = 0; ks < 2; ++ks) {
            const int k0 = ks * 16;
            uint32_t af[4][4];
            #pragma unroll
            for (int i = 0; i < 4; ++i) {
                uint32_t ad = asb + ((wm + i * 16 + a_r) * AST + k0 + a_k) * 2;
                ldsm_x4(af[i][0], af[i][1], af[i][2], af[i][3], ad);
            }
            uint32_t bf[4][2];
            #pragma unroll
            for (int jp = 0; jp < 2; ++jp) {
                uint32_t bd = bsb + ((k0 + b_k) * BST + wn + jp * 16 + b_n) * 2;
                ldsm_x4t(bf[jp * 2][0], bf[jp * 2][1],
                         bf[jp * 2 + 1][0], bf[jp * 2 + 1][1], bd);
            }
            #pragma unroll
            for (int i = 0; i < 4; ++i)
                #pragma unroll
                for (int j = 0; j < 4; ++j)
                    mma_f16(acc[i][j][0], acc[i][j][1], acc[i][j][2], acc[i][j][3],
                            af[i][0], af[i][1], af[i][2], af[i][3],
                            bf[j][0], bf[j][1]);
        }
        __syncthreads();
    }

    const float* bp = b1 + (size_t)e * FF + n0;
    #pragma unroll
    for (int j = 0; j < 4; ++j) {
        int col = wn + j * 8 + (lane & 3) * 2;
        float bb0 = bp[col], bb1 = bp[col + 1];
        #pragma unroll
        for (int i = 0; i < 4; ++i) {
            int r0 = row0 + wm + i * 16 + qr;
            float a0 = acc[i][j][0] + bb0, a1 = acc[i][j][1] + bb1;
            uint32_t p0 = pack_h2(a0 / (1.f + __expf(-a0)), a1 / (1.f + __expf(-a1)));
            *(uint32_t*)&g_Hh[(size_t)r0 * FF + n0 + col] = p0;
            float a2 = acc[i][j][2] + bb0, a3 = acc[i][j][3] + bb1;
            uint32_t p1 = pack_h2(a2 / (1.f + __expf(-a2)), a3 / (1.f + __expf(-a3)));
            *(uint32_t*)&g_Hh[(size_t)(r0 + 8) * FF + n0 + col] = p1;
        }
    }
}

__global__ void __launch_bounds__(256, 2) k_mma_gemm2(
    const float* __restrict__ b2, float* __restrict__ out)
{
    extern __shared__ __half sm[];
    __half* As = sm;
    __half* Bs = sm + NSTAGE * A_STAGE_H;
    __shared__ int   stok[128];
    __shared__ float ssc[128];

    const int tid = threadIdx.x;
    const int n0 = blockIdx.x * 128;
    const int row0 = blockIdx.y * 128;
    const int e = tile_expert(row0);
    if (e < 0) return;
    const __half* __restrict__ w = g_w2h + (size_t)e * FF * DIM;

    if (tid < 128) { stok[tid] = g_pair_tok[row0 + tid]; ssc[tid] = g_pair_sc[row0 + tid]; }
    __syncthreads();

    const int lane = tid & 31;
    const int wrp = tid >> 5;
    const int wm = (wrp & 1) * 64;
    const int wn = (wrp >> 1) * 32;
    const int qr = lane >> 2;
    const uint32_t as_base = smem_u32(As);
    const uint32_t bs_base = smem_u32(Bs);

    const int ar = tid >> 2;
    const int ac8 = (tid & 3) * 8;
    const __half* hr0 = g_Hh + (size_t)(row0 + ar) * FF + ac8;
    const __half* hr1 = g_Hh + (size_t)(row0 + ar + 64) * FF + ac8;
    const int br = tid >> 4;
    const int bc8 = (tid & 15) * 8;
    const __half* wr = w + n0 + bc8;

    const uint32_t a_d0 = as_base + (ar * AST + ac8) * 2;
    const uint32_t a_d1 = as_base + ((ar + 64) * AST + ac8) * 2;
    const uint32_t b_d0 = bs_base + (br * BST + bc8) * 2;
    const uint32_t b_d1 = bs_base + ((br + 16) * BST + bc8) * 2;

    const int a_r = (lane & 15);
    const int a_k = (lane & 16) >> 1;
    const int b_k = (lane & 7) + ((lane & 8) ? 8 : 0);
    const int b_n = (lane & 16) >> 1;

    float acc[4][4][4];
    #pragma unroll
    for (int i = 0; i < 4; i++)
        #pragma unroll
        for (int j = 0; j < 4; j++)
            #pragma unroll
            for (int q = 0; q < 4; q++) acc[i][j][q] = 0.f;

    const int NK = FF / 32;
    #pragma unroll
    for (int s = 0; s < NSTAGE - 1; ++s) {
        int kt = s * 32;
        uint32_t ao = s * A_STAGE_H * 2, bo = s * B_STAGE_H * 2;
        cpa16(a_d0 + ao, hr0 + kt);
        cpa16(a_d1 + ao, hr1 + kt);
        cpa16(b_d0 + bo, wr + (size_t)(kt + br) * DIM);
        cpa16(b_d1 + bo, wr + (size_t)(kt + br + 16) * DIM);
        CP_COMMIT();
    }

    for (int ki = 0; ki < NK; ++ki) {
        int kf = ki + NSTAGE - 1;
        if (kf < NK) {
            int s = kf % NSTAGE;
            int kt = kf * 32;
            uint32_t ao = s * A_STAGE_H * 2, bo = s * B_STAGE_H * 2;
            cpa16(a_d0 + ao, hr0 + kt);
            cpa16(a_d1 + ao, hr1 + kt);
            cpa16(b_d0 + bo, wr + (size_t)(kt + br) * DIM);
            cpa16(b_d1 + bo, wr + (size_t)(kt + br + 16) * DIM);
        }
        CP_COMMIT();
        CP_WAITN();
        __syncthreads();

        const int s = ki % NSTAGE;
        const uint32_t asb = as_base + s * A_STAGE_H * 2;
        const uint32_t bsb = bs_base + s * B_STAGE_H * 2;
        #pragma unroll
        for (int ks = 0; ks < 2; ++ks) {
            const int k0 = ks * 16;
            uint32_t af[4][4];
            #pragma unroll
            for (int i = 0; i < 4; ++i) {
                uint32_t ad = asb + ((wm + i * 16 + a_r) * AST + k0 + a_k) * 2;
                ldsm_x4(af[i][0], af[i][1], af[i][2], af[i][3], ad);
            }
            uint32_t bf[4][2];
            #pragma unroll
            for (int jp = 0; jp < 2; ++jp) {
                uint32_t bd = bsb + ((k0 + b_k) * BST + wn + jp * 16 + b_n) * 2;
                ldsm_x4t(bf[jp * 2][0], bf[jp * 2][1],
                         bf[jp * 2 + 1][0], bf[jp * 2 + 1][1], bd);
            }
            #pragma unroll
            for (int i = 0; i < 4; ++i)
                #pragma unroll
                for (int j = 0; j < 4; ++j)
                    mma_f16(acc[i][j][0], acc[i][j][1], acc[i][j][2], acc[i][j][3],
                            af[i][0], af[i][1], af[i][2], af[i][3],
                            bf[j][0], bf[j][1]);
        }
        __syncthreads();
    }

    const float* bp = b2 + (size_t)e * DIM + n0;
    #pragma unroll
    for (int j = 0; j < 4; ++j) {
        int col = wn + j * 8 + (lane & 3) * 2;
        float bb0 = bp[col], bb1 = bp[col + 1];
        #pragma unroll
        for (int i = 0; i < 4; ++i) {
            int m = wm + i * 16 + qr;
            int t0 = stok[m], t1 = stok[m + 8];
            if (t0 >= 0) {
                float s = ssc[m];
                atomicAdd(&out[(size_t)t0 * DIM + n0 + col],     s * (acc[i][j][0] + bb0));
                atomicAdd(&out[(size_t)t0 * DIM + n0 + col + 1], s * (acc[i][j][1] + bb1));
            }
            if (t1 >= 0) {
                float s = ssc[m + 8];
                atomicAdd(&out[(size_t)t1 * DIM + n0 + col],     s * (acc[i][j][2] + bb0));
                atomicAdd(&out[(size_t)t1 * DIM + n0 + col + 1], s * (acc[i][j][3] + bb1));
            }
        }
    }
}

// ---------------- aux loss ---------------------------------------------------
__global__ void __launch_bounds__(256) k_aux(float* __restrict__ aux_out) {
    __shared__ float sred[256];
    __shared__ float simp[NE];
    int tid = threadIdx.x;
    float imp[NE];
    #pragma unroll
    for (int e = 0; e < NE; e++) imp[e] = 0.f;
    for (int t = tid; t < T_TOK; t += 256) {
        imp[g_tok_e[2 * t]]     += g_tok_p[2 * t];
        imp[g_tok_e[2 * t + 1]] += g_tok_p[2 * t + 1];
    }
    for (int e = 0; e < NE; e++) {
        sred[tid] = imp[e];
        __syncthreads();
        for (int off = 128; off > 0; off >>= 1) {
            if (tid < off) sred[tid] += sred[tid + off];
            __syncthreads();
        }
        if (tid == 0) simp[e] = sred[0] / (float)T_TOK;
        __syncthreads();
    }
    if (tid == 0) {
        float aux = 0.f;
        const float u = 1.f / (float)NE;
        const float logu = logf(u);
        #pragma unroll
        for (int e = 0; e < NE; e++)
            aux += u * (logu - logf(simp[e] + 1e-8f));
        aux_out[0] = aux;
    }
}

// ---------------- launch -----------------------------------------------------
extern "C" void kernel_launch(void* const* d_in, const int* in_sizes, int n_in,
                              void* d_out, int out_size) {
    const float* x       = (const float*)d_in[0];
    const float* noise   = (const float*)d_in[1];
    const float* gate_w  = (const float*)d_in[2];
    const float* gate_b  = (const float*)d_in[3];
    const float* noise_w = (const float*)d_in[4];
    const float* noise_b = (const float*)d_in[5];
    const float* w1      = (const float*)d_in[6];
    const float* b1      = (const float*)d_in[7];
    const float* w2      = (const float*)d_in[8];
    const float* b2      = (const float*)d_in[9];
    float* out = (float*)d_out;
    (void)in_sizes; (void)n_in;

    static cudaStream_t s2;
    static cudaEvent_t ev_fork, ev_join;
    static bool init_done = false;
    if (!init_done) {
        cudaFuncSetAttribute(k_mma_gemm1, cudaFuncAttributeMaxDynamicSharedMemorySize, GEMM_SMEM);
        cudaFuncSetAttribute(k_mma_gemm2, cudaFuncAttributeMaxDynamicSharedMemorySize, GEMM_SMEM);
        cudaStreamCreateWithFlags(&s2, cudaStreamNonBlocking);
        cudaEventCreateWithFlags(&ev_fork, cudaEventDisableTiming);
        cudaEventCreateWithFlags(&ev_join, cudaEventDisableTiming);
        init_done = true;
    }

    __half* d_w1h; cudaGetSymbolAddress((void**)&d_w1h, g_w1h);
    __half* d_w2h; cudaGetSymbolAddress((void**)&d_w2h, g_w2h);

    // fork: weight conversion on s2, overlapped with router chain on main
    cudaEventRecord(ev_fork, 0);
    cudaStreamWaitEvent(s2, ev_fork, 0);
    {
        int n8 = NE * DIM * FF / 8;
        k_cvtw<<<(2 * n8 + 255) / 256, 256, 0, s2>>>(
            (const float4*)w1, (const float4*)w2, (uint4*)d_w1h, (uint4*)d_w2h);
    }
    cudaEventRecord(ev_join, s2);

    k_setup<<<(T_TOK * DIM / 4 + 255) / 256, 256>>>((float4*)out, gate_w, noise_w);
    k_router<<<T_TOK / 8, 256>>>(x, noise, gate_b, noise_b);
    k_offsets<<<1, 32>>>();
    k_scatter<<<(NPAIR + 255) / 256, 256>>>();

    // join: GEMMs need converted weights
    cudaStreamWaitEvent(0, ev_join, 0);
    k_mma_gemm1<<<dim3(FF / 128, CAPP / 128), 256, GEMM_SMEM>>>(b1);
    k_mma_gemm2<<<dim3(DIM / 128, CAPP / 128), 256, GEMM_SMEM>>>(b2, out);
    k_aux<<<1, 256>>>(out + (out_size - 1));
}

// round 10
// speedup vs baseline: 1.0915x; 1.0243x over previous
#include <cuda_runtime.h>
#include <cuda_fp16.h>
#include <math.h>
#include <stdint.h>

#define T_TOK 4096
#define DIM   1024
#define NE    8
#define FF    4096
#define NPAIR (2*T_TOK)
#define CAPP  9216             // 8192 + 8*128 padding (segments 128-aligned)

// ---------------- scratch (device globals) ----------------------------------
__device__ __half g_Hh[(size_t)CAPP * FF];
__device__ __half g_xh[(size_t)T_TOK * DIM];
__device__ __half g_w1h[(size_t)NE * DIM * FF];
__device__ __half g_w2h[(size_t)NE * FF * DIM];
__device__ float g_gwc[DIM * NE];          // gate_w + noise_w combined
__device__ int   g_pair_tok[CAPP];
__device__ float g_pair_sc[CAPP];
__device__ int   g_tok_e[NPAIR];
__device__ float g_tok_p[NPAIR];
__device__ int   g_counts[NE];
__device__ int   g_cursor[NE];

// ---------------- helpers ----------------------------------------------------
__device__ __forceinline__ uint32_t smem_u32(const void* p) {
    return (uint32_t)__cvta_generic_to_shared(p);
}
__device__ __forceinline__ uint32_t pack_h2(float a, float b) {
    __half2 h = __floats2half2_rn(a, b);
    return *(uint32_t*)&h;
}
__device__ __forceinline__ void mma_f16(float& c0, float& c1, float& c2, float& c3,
                                        uint32_t a0, uint32_t a1, uint32_t a2, uint32_t a3,
                                        uint32_t b0, uint32_t b1) {
    asm volatile(
        "mma.sync.aligned.m16n8k16.row.col.f32.f16.f16.f32 "
        "{%0,%1,%2,%3}, {%4,%5,%6,%7}, {%8,%9}, {%0,%1,%2,%3};"
        : "+f"(c0), "+f"(c1), "+f"(c2), "+f"(c3)
        : "r"(a0), "r"(a1), "r"(a2), "r"(a3), "r"(b0), "r"(b1));
}
__device__ __forceinline__ void ldsm_x4(uint32_t& r0, uint32_t& r1, uint32_t& r2,
                                        uint32_t& r3, uint32_t addr) {
    asm volatile("ldmatrix.sync.aligned.m8n8.x4.shared.b16 {%0,%1,%2,%3}, [%4];"
                 : "=r"(r0), "=r"(r1), "=r"(r2), "=r"(r3) : "r"(addr));
}
__device__ __forceinline__ void ldsm_x4t(uint32_t& r0, uint32_t& r1, uint32_t& r2,
                                         uint32_t& r3, uint32_t addr) {
    asm volatile("ldmatrix.sync.aligned.m8n8.x4.trans.shared.b16 {%0,%1,%2,%3}, [%4];"
                 : "=r"(r0), "=r"(r1), "=r"(r2), "=r"(r3) : "r"(addr));
}
__device__ __forceinline__ void cpa16(uint32_t dst, const void* src) {
    asm volatile("cp.async.cg.shared.global [%0], [%1], 16;"
                 :: "r"(dst), "l"(src));
}
#define CP_COMMIT() asm volatile("cp.async.commit_group;" ::: "memory")
#define CP_WAIT3()  asm volatile("cp.async.wait_group 3;"  ::: "memory")

// ---------------- setup kernels ---------------------------------------------
__global__ void k_setup(float4* out, const float* __restrict__ gw,
                        const float* __restrict__ nw) {
    int i = blockIdx.x * blockDim.x + threadIdx.x;
    if (i < T_TOK * DIM / 4) out[i] = make_float4(0.f, 0.f, 0.f, 0.f);
    if (i < CAPP) { g_pair_tok[i] = -1; g_pair_sc[i] = 0.f; }
    if (i < DIM * NE) g_gwc[i] = gw[i] + nw[i];
    if (i < NE) { g_counts[i] = 0; g_cursor[i] = 0; }
}
// fp32 -> fp16 bulk convert of BOTH weight tensors in one launch
__global__ void k_cvtw(const float4* __restrict__ w1, const float4* __restrict__ w2,
                       uint4* __restrict__ d1, uint4* __restrict__ d2) {
    const int n8 = NE * DIM * FF / 8;
    int i = blockIdx.x * blockDim.x + threadIdx.x;
    const float4* src; uint4* dst;
    if (i < n8) { src = w1; dst = d1; }
    else        { i -= n8; src = w2; dst = d2; }
    float4 v0 = src[2 * i], v1 = src[2 * i + 1];
    dst[i] = make_uint4(pack_h2(v0.x, v0.y), pack_h2(v0.z, v0.w),
                        pack_h2(v1.x, v1.y), pack_h2(v1.z, v1.w));
}

// ---------------- router: 8 tokens / 256-thread block ------------------------
__global__ void __launch_bounds__(256) k_router(
    const float* __restrict__ x, const float* __restrict__ noise,
    const float* __restrict__ gb, const float* __restrict__ nb)
{
    __shared__ float sx[8 * DIM];   // 32 KB
    __shared__ float sl[64];
    const int tid = threadIdx.x;
    const int t0 = blockIdx.x * 8;

    for (int i = tid; i < 8 * DIM / 4; i += 256) {
        float4 v = ((const float4*)(x + (size_t)t0 * DIM))[i];
        *(float4*)&sx[i * 4] = v;
    }
    __syncthreads();
    // x -> fp16
    for (int i = tid; i < 8 * DIM / 2; i += 256) {
        *(uint32_t*)&g_xh[(size_t)t0 * DIM + 2 * i] = pack_h2(sx[2 * i], sx[2 * i + 1]);
    }
    // logits: pair p = (token, expert), 4 threads per pair
    const int p = tid >> 2;
    const int q = tid & 3;
    const int tok = p >> 3, e = p & 7;
    const float* xr = &sx[tok * DIM];
    float s = 0.f;
    #pragma unroll 4
    for (int k = q; k < DIM; k += 4)
        s += xr[k] * g_gwc[k * NE + e];
    s += __shfl_down_sync(0xffffffffu, s, 1);
    s += __shfl_down_sync(0xffffffffu, s, 2);
    if (q == 0) sl[p] = s;
    __syncthreads();

    if (tid < 8) {
        int t = t0 + tid;
        float lg[NE];
        #pragma unroll
        for (int k = 0; k < NE; k++)
            lg[k] = sl[tid * NE + k] + gb[k] + nb[k] + noise[t * NE + k];
        float v0 = -1e30f; int i0 = 0;
        #pragma unroll
        for (int k = 0; k < NE; k++) { if (lg[k] > v0) { v0 = lg[k]; i0 = k; } }
        float v1 = -1e30f; int i1 = 0;
        #pragma unroll
        for (int k = 0; k < NE; k++) { if (k == i0) continue; if (lg[k] > v1) { v1 = lg[k]; i1 = k; } }
        float e1 = expf(v1 - v0);
        float z = 1.f + e1;
        g_tok_e[2 * t] = i0;  g_tok_e[2 * t + 1] = i1;
        g_tok_p[2 * t] = 1.f / z;  g_tok_p[2 * t + 1] = e1 / z;
        atomicAdd(&g_counts[i0], 1);
        atomicAdd(&g_counts[i1], 1);
    }
}

// ---------------- inline segment offsets (8 ints, computed per consumer) -----
__device__ __forceinline__ int seg_start(int e) {
    int acc = 0;
    #pragma unroll
    for (int i = 0; i < NE; i++)
        if (i < e) acc += ((g_counts[i] + 127) >> 7) << 7;
    return acc;
}
__device__ __forceinline__ int tile_expert(int row0) {
    int acc = 0, e = -1;
    #pragma unroll
    for (int i = 0; i < NE; i++) {
        int pad = ((g_counts[i] + 127) >> 7) << 7;
        if (row0 >= acc && row0 < acc + pad) e = i;
        acc += pad;
    }
    return e;
}

__global__ void k_scatter() {
    int i = blockIdx.x * blockDim.x + threadIdx.x;
    if (i >= NPAIR) return;
    int t = i >> 1;
    int e = g_tok_e[i];
    float p = g_tok_p[i];
    int pos = seg_start(e) + atomicAdd(&g_cursor[e], 1);
    g_pair_tok[pos] = t;
    g_pair_sc[pos]  = p;
}

// ---------------- SMEM geometry (halfs) --------------------------------------
#define AST 40
#define BST 136
#define A_STAGE_H (128 * AST)    // 5120 halfs
#define B_STAGE_H (32 * BST)     // 4352 halfs
#define NSTAGE 4
#define GEMM_SMEM ((A_STAGE_H + B_STAGE_H) * NSTAGE * 2)   // 75776 B

// =============================================================================
// fp16 mma.sync GEMM, 128x128 CTA tile, 8 warps, K-tile 32, 4-stage cp.async
// (R7-proven configuration)
// =============================================================================

__global__ void __launch_bounds__(256, 2) k_mma_gemm1(const float* __restrict__ b1)
{
    extern __shared__ __half sm[];
    __half* As = sm;
    __half* Bs = sm + NSTAGE * A_STAGE_H;
    __shared__ int stok[128];

    const int tid = threadIdx.x;
    const int n0 = blockIdx.x * 128;
    const int row0 = blockIdx.y * 128;
    const int e = tile_expert(row0);
    if (e < 0) return;
    const __half* __restrict__ w = g_w1h + (size_t)e * DIM * FF;

    if (tid < 128) stok[tid] = g_pair_tok[row0 + tid];
    __syncthreads();

    const int lane = tid & 31;
    const int wrp = tid >> 5;
    const int wm = (wrp & 1) * 64;
    const int wn = (wrp >> 1) * 32;
    const int qr = lane >> 2;
    const uint32_t as_base = smem_u32(As);
    const uint32_t bs_base = smem_u32(Bs);

    const int ar = tid >> 2;
    const int ac8 = (tid & 3) * 8;
    int ta0 = stok[ar];      if (ta0 < 0) ta0 = 0;
    int ta1 = stok[ar + 64]; if (ta1 < 0) ta1 = 0;
    const __half* xr0 = g_xh + (size_t)ta0 * DIM + ac8;
    const __half* xr1 = g_xh + (size_t)ta1 * DIM + ac8;
    const int br = tid >> 4;
    const int bc8 = (tid & 15) * 8;
    const __half* wr = w + n0 + bc8;

    const uint32_t a_d0 = as_base + (ar * AST + ac8) * 2;
    const uint32_t a_d1 = as_base + ((ar + 64) * AST + ac8) * 2;
    const uint32_t b_d0 = bs_base + (br * BST + bc8) * 2;
    const uint32_t b_d1 = bs_base + ((br + 16) * BST + bc8) * 2;

    const int a_r = (lane & 15);
    const int a_k = (lane & 16) >> 1;
    const int b_k = (lane & 7) + ((lane & 8) ? 8 : 0);
    const int b_n = (lane & 16) >> 1;

    float acc[4][4][4];
    #pragma unroll
    for (int i = 0; i < 4; i++)
        #pragma unroll
        for (int j = 0; j < 4; j++)
            #pragma unroll
            for (int q = 0; q < 4; q++) acc[i][j][q] = 0.f;

    const int NK = DIM / 32;
    #pragma unroll
    for (int s = 0; s < NSTAGE - 1; ++s) {
        int kt = s * 32;
        uint32_t ao = s * A_STAGE_H * 2, bo = s * B_STAGE_H * 2;
        cpa16(a_d0 + ao, xr0 + kt);
        cpa16(a_d1 + ao, xr1 + kt);
        cpa16(b_d0 + bo, wr + (size_t)(kt + br) * FF);
        cpa16(b_d1 + bo, wr + (size_t)(kt + br + 16) * FF);
        CP_COMMIT();
    }

    for (int ki = 0; ki < NK; ++ki) {
        int kf = ki + NSTAGE - 1;
        if (kf < NK) {
            int s = kf % NSTAGE;
            int kt = kf * 32;
            uint32_t ao = s * A_STAGE_H * 2, bo = s * B_STAGE_H * 2;
            cpa16(a_d0 + ao, xr0 + kt);
            cpa16(a_d1 + ao, xr1 + kt);
            cpa16(b_d0 + bo, wr + (size_t)(kt + br) * FF);
            cpa16(b_d1 + bo, wr + (size_t)(kt + br + 16) * FF);
        }
        CP_COMMIT();
        CP_WAIT3();
        __syncthreads();

        const int s = ki % NSTAGE;
        const uint32_t asb = as_base + s * A_STAGE_H * 2;
        const uint32_t bsb = bs_base + s * B_STAGE_H * 2;
        #pragma unroll
        for (int ks = 0; ks < 2; ++ks) {
            const int k0 = ks * 16;
            uint32_t af[4][4];
            #pragma unroll
            for (int i = 0; i < 4; ++i) {
                uint32_t ad = asb + ((wm + i * 16 + a_r) * AST + k0 + a_k) * 2;
                ldsm_x4(af[i][0], af[i][1], af[i][2], af[i][3], ad);
            }
            uint32_t bf[4][2];
            #pragma unroll
            for (int jp = 0; jp < 2; ++jp) {
                uint32_t bd = bsb + ((k0 + b_k) * BST + wn + jp * 16 + b_n) * 2;
                ldsm_x4t(bf[jp * 2][0], bf[jp * 2][1],
                         bf[jp * 2 + 1][0], bf[jp * 2 + 1][1], bd);
            }
            #pragma unroll
            for (int i = 0; i < 4; ++i)
                #pragma unroll
                for (int j = 0; j < 4; ++j)
                    mma_f16(acc[i][j][0], acc[i][j][1], acc[i][j][2], acc[i][j][3],
                            af[i][0], af[i][1], af[i][2], af[i][3],
                            bf[j][0], bf[j][1]);
        }
        __syncthreads();
    }

    const float* bp = b1 + (size_t)e * FF + n0;
    #pragma unroll
    for (int j = 0; j < 4; ++j) {
        int col = wn + j * 8 + (lane & 3) * 2;
        float bb0 = bp[col], bb1 = bp[col + 1];
        #pragma unroll
        for (int i = 0; i < 4; ++i) {
            int r0 = row0 + wm + i * 16 + qr;
            float a0 = acc[i][j][0] + bb0, a1 = acc[i][j][1] + bb1;
            uint32_t p0 = pack_h2(a0 / (1.f + __expf(-a0)), a1 / (1.f + __expf(-a1)));
            *(uint32_t*)&g_Hh[(size_t)r0 * FF + n0 + col] = p0;
            float a2 = acc[i][j][2] + bb0, a3 = acc[i][j][3] + bb1;
            uint32_t p1 = pack_h2(a2 / (1.f + __expf(-a2)), a3 / (1.f + __expf(-a3)));
            *(uint32_t*)&g_Hh[(size_t)(r0 + 8) * FF + n0 + col] = p1;
        }
    }
}

__global__ void __launch_bounds__(256, 2) k_mma_gemm2(
    const float* __restrict__ b2, float* __restrict__ out)
{
    extern __shared__ __half sm[];
    __half* As = sm;
    __half* Bs = sm + NSTAGE * A_STAGE_H;
    __shared__ int   stok[128];
    __shared__ float ssc[128];

    const int tid = threadIdx.x;
    const int n0 = blockIdx.x * 128;
    const int row0 = blockIdx.y * 128;
    const int e = tile_expert(row0);
    if (e < 0) return;
    const __half* __restrict__ w = g_w2h + (size_t)e * FF * DIM;

    if (tid < 128) { stok[tid] = g_pair_tok[row0 + tid]; ssc[tid] = g_pair_sc[row0 + tid]; }
    __syncthreads();

    const int lane = tid & 31;
    const int wrp = tid >> 5;
    const int wm = (wrp & 1) * 64;
    const int wn = (wrp >> 1) * 32;
    const int qr = lane >> 2;
    const uint32_t as_base = smem_u32(As);
    const uint32_t bs_base = smem_u32(Bs);

    const int ar = tid >> 2;
    const int ac8 = (tid & 3) * 8;
    const __half* hr0 = g_Hh + (size_t)(row0 + ar) * FF + ac8;
    const __half* hr1 = g_Hh + (size_t)(row0 + ar + 64) * FF + ac8;
    const int br = tid >> 4;
    const int bc8 = (tid & 15) * 8;
    const __half* wr = w + n0 + bc8;

    const uint32_t a_d0 = as_base + (ar * AST + ac8) * 2;
    const uint32_t a_d1 = as_base + ((ar + 64) * AST + ac8) * 2;
    const uint32_t b_d0 = bs_base + (br * BST + bc8) * 2;
    const uint32_t b_d1 = bs_base + ((br + 16) * BST + bc8) * 2;

    const int a_r = (lane & 15);
    const int a_k = (lane & 16) >> 1;
    const int b_k = (lane & 7) + ((lane & 8) ? 8 : 0);
    const int b_n = (lane & 16) >> 1;

    float acc[4][4][4];
    #pragma unroll
    for (int i = 0; i < 4; i++)
        #pragma unroll
        for (int j = 0; j < 4; j++)
            #pragma unroll
            for (int q = 0; q < 4; q++) acc[i][j][q] = 0.f;

    const int NK = FF / 32;
    #pragma unroll
    for (int s = 0; s < NSTAGE - 1; ++s) {
        int kt = s * 32;
        uint32_t ao = s * A_STAGE_H * 2, bo = s * B_STAGE_H * 2;
        cpa16(a_d0 + ao, hr0 + kt);
        cpa16(a_d1 + ao, hr1 + kt);
        cpa16(b_d0 + bo, wr + (size_t)(kt + br) * DIM);
        cpa16(b_d1 + bo, wr + (size_t)(kt + br + 16) * DIM);
        CP_COMMIT();
    }

    for (int ki = 0; ki < NK; ++ki) {
        int kf = ki + NSTAGE - 1;
        if (kf < NK) {
            int s = kf % NSTAGE;
            int kt = kf * 32;
            uint32_t ao = s * A_STAGE_H * 2, bo = s * B_STAGE_H * 2;
            cpa16(a_d0 + ao, hr0 + kt);
            cpa16(a_d1 + ao, hr1 + kt);
            cpa16(b_d0 + bo, wr + (size_t)(kt + br) * DIM);
            cpa16(b_d1 + bo, wr + (size_t)(kt + br + 16) * DIM);
        }
        CP_COMMIT();
        CP_WAIT3();
        __syncthreads();

        const int s = ki % NSTAGE;
        const uint32_t asb = as_base + s * A_STAGE_H * 2;
        const uint32_t bsb = bs_base + s * B_STAGE_H * 2;
        #pragma unroll
        for (int ks = 0; ks < 2; ++ks) {
            const int k0 = ks * 16;
            uint32_t af[4][4];
            #pragma unroll
            for (int i = 0; i < 4; ++i) {
                uint32_t ad = asb + ((wm + i * 16 + a_r) * AST + k0 + a_k) * 2;
                ldsm_x4(af[i][0], af[i][1], af[i][2], af[i][3], ad);
            }
            uint32_t bf[4][2];
            #pragma unroll
            for (int jp = 0; jp < 2; ++jp) {
                uint32_t bd = bsb + ((k0 + b_k) * BST + wn + jp * 16 + b_n) * 2;
                ldsm_x4t(bf[jp * 2][0], bf[jp * 2][1],
                         bf[jp * 2 + 1][0], bf[jp * 2 + 1][1], bd);
            }
            #pragma unroll
            for (int i = 0; i < 4; ++i)
                #pragma unroll
                for (int j = 0; j < 4; ++j)
                    mma_f16(acc[i][j][0], acc[i][j][1], acc[i][j][2], acc[i][j][3],
                            af[i][0], af[i][1], af[i][2], af[i][3],
                            bf[j][0], bf[j][1]);
        }
        __syncthreads();
    }

    const float* bp = b2 + (size_t)e * DIM + n0;
    #pragma unroll
    for (int j = 0; j < 4; ++j) {
        int col = wn + j * 8 + (lane & 3) * 2;
        float bb0 = bp[col], bb1 = bp[col + 1];
        #pragma unroll
        for (int i = 0; i < 4; ++i) {
            int m = wm + i * 16 + qr;
            int t0 = stok[m], t1 = stok[m + 8];
            if (t0 >= 0) {
                float s = ssc[m];
                atomicAdd(&out[(size_t)t0 * DIM + n0 + col],     s * (acc[i][j][0] + bb0));
                atomicAdd(&out[(size_t)t0 * DIM + n0 + col + 1], s * (acc[i][j][1] + bb1));
            }
            if (t1 >= 0) {
                float s = ssc[m + 8];
                atomicAdd(&out[(size_t)t1 * DIM + n0 + col],     s * (acc[i][j][2] + bb0));
                atomicAdd(&out[(size_t)t1 * DIM + n0 + col + 1], s * (acc[i][j][3] + bb1));
            }
        }
    }
}

// ---------------- aux loss ---------------------------------------------------
__global__ void __launch_bounds__(256) k_aux(float* __restrict__ aux_out) {
    __shared__ float sred[256];
    __shared__ float simp[NE];
    int tid = threadIdx.x;
    float imp[NE];
    #pragma unroll
    for (int e = 0; e < NE; e++) imp[e] = 0.f;
    for (int t = tid; t < T_TOK; t += 256) {
        imp[g_tok_e[2 * t]]     += g_tok_p[2 * t];
        imp[g_tok_e[2 * t + 1]] += g_tok_p[2 * t + 1];
    }
    for (int e = 0; e < NE; e++) {
        sred[tid] = imp[e];
        __syncthreads();
        for (int off = 128; off > 0; off >>= 1) {
            if (tid < off) sred[tid] += sred[tid + off];
            __syncthreads();
        }
        if (tid == 0) simp[e] = sred[0] / (float)T_TOK;
        __syncthreads();
    }
    if (tid == 0) {
        float aux = 0.f;
        const float u = 1.f / (float)NE;
        const float logu = logf(u);
        #pragma unroll
        for (int e = 0; e < NE; e++)
            aux += u * (logu - logf(simp[e] + 1e-8f));
        aux_out[0] = aux;
    }
}

// ---------------- launch -----------------------------------------------------
extern "C" void kernel_launch(void* const* d_in, const int* in_sizes, int n_in,
                              void* d_out, int out_size) {
    const float* x       = (const float*)d_in[0];
    const float* noise   = (const float*)d_in[1];
    const float* gate_w  = (const float*)d_in[2];
    const float* gate_b  = (const float*)d_in[3];
    const float* noise_w = (const float*)d_in[4];
    const float* noise_b = (const float*)d_in[5];
    const float* w1      = (const float*)d_in[6];
    const float* b1      = (const float*)d_in[7];
    const float* w2      = (const float*)d_in[8];
    const float* b2      = (const float*)d_in[9];
    float* out = (float*)d_out;
    (void)in_sizes; (void)n_in;

    static bool init_done = false;
    if (!init_done) {
        cudaFuncSetAttribute(k_mma_gemm1, cudaFuncAttributeMaxDynamicSharedMemorySize, GEMM_SMEM);
        cudaFuncSetAttribute(k_mma_gemm2, cudaFuncAttributeMaxDynamicSharedMemorySize, GEMM_SMEM);
        init_done = true;
    }

    __half* d_w1h; cudaGetSymbolAddress((void**)&d_w1h, g_w1h);
    __half* d_w2h; cudaGetSymbolAddress((void**)&d_w2h, g_w2h);

    {
        int n8 = NE * DIM * FF / 8;
        k_cvtw<<<(2 * n8 + 255) / 256, 256>>>(
            (const float4*)w1, (const float4*)w2, (uint4*)d_w1h, (uint4*)d_w2h);
    }
    k_setup<<<(T_TOK * DIM / 4 + 255) / 256, 256>>>((float4*)out, gate_w, noise_w);
    k_router<<<T_TOK / 8, 256>>>(x, noise, gate_b, noise_b);
    k_scatter<<<(NPAIR + 255) / 256, 256>>>();
    k_mma_gemm1<<<dim3(FF / 128, CAPP / 128), 256, GEMM_SMEM>>>(b1);
    k_mma_gemm2<<<dim3(DIM / 128, CAPP / 128), 256, GEMM_SMEM>>>(b2, out);
    k_aux<<<1, 256>>>(out + (out_size - 1));
}